// round 5
// baseline (speedup 1.0000x reference)
#include <cuda_runtime.h>
#include <math.h>

typedef unsigned long long ull;

#define TPB 128

// 8 MB static scratch: [b][32] = 30 lrelu'd conv2 outputs + 2 zero pads
__device__ float g_scratch[65536 * 32];

// ---------------- K1 shared memory (floats) ----------------
#define W1_OFF   0        // conv1 [half][c][tap][12] : 2*21*9*12 = 4536
#define W2_OFF   4536     // conv2 [oc][q][oc2 pad32] : 20*4*32  = 2560
#define B1_OFF   7096     // 20
#define B2P_OFF  7116     // 32
#define FB_OFF   7148     // per-thread 21-float feature buffer
#define K1_FLOATS (FB_OFF + TPB * 21)      // 9836
#define K1_BYTES  (K1_FLOATS * 4)          // 39344 -> 3 blocks/SM

// ---------------- K2 shared memory (floats) ----------------
#define FC1P_OFF  0        // fc1 [j1][32] (cols 0..29, pad 0) : 3840
#define FC1OH_OFF 3840     // fc1 one-hot cols [j1][8] : 960
#define FC2T_OFF  4800     // fc2 transposed [j1][84] : 10080
#define FC3_OFF   14880    // 84
#define FB1_OFF   14964    // 120
#define FB2_OFF   15084    // 84
#define FB3_OFF   15168    // 1 (+3 pad)
#define K2_FLOATS 15172
#define K2_BYTES  (K2_FLOATS * 4)          // 60688 -> 3 blocks/SM

__device__ __forceinline__ ull ffma2(ull a, ull b, ull c) {
    ull d; asm("fma.rn.f32x2 %0,%1,%2,%3;" : "=l"(d) : "l"(a), "l"(b), "l"(c)); return d;
}
__device__ __forceinline__ ull pack2(float lo, float hi) {
    ull d; asm("mov.b64 %0,{%1,%2};" : "=l"(d) : "f"(lo), "f"(hi)); return d;
}
__device__ __forceinline__ void unpack2(ull v, float& lo, float& hi) {
    asm("mov.b64 {%0,%1},%2;" : "=f"(lo), "=f"(hi) : "l"(v));
}
__device__ __forceinline__ float lrelu(float v) { return fmaxf(v, 0.2f * v); }

// conv1 (one 10-oc half) contribution of the neighbor at grid position (PY,PX).
// weights at wb laid out [c][tap][12] (10 used, 2 pad). Loop-shaped on purpose
// (partial unroll) — proven non-spilling codegen.
template<int PY, int PX>
__device__ __forceinline__ void nconvh(const float* __restrict__ wb,
                                       const float* __restrict__ Fb,
                                       ull (&o2)[5][9]) {
#pragma unroll 3
    for (int c = 0; c < 21; ++c) {
        float fv = Fb[c];
        ull fc = pack2(fv, fv);
#pragma unroll
        for (int dy = -1; dy <= 1; ++dy) {
            if (PY + dy < 0 || PY + dy > 2) continue;
#pragma unroll
            for (int dx = -1; dx <= 1; ++dx) {
                if (PX + dx < 0 || PX + dx > 2) continue;
                const int tap = (1 - dy) * 3 + (1 - dx);
                const int q = (PY + dy) * 3 + (PX + dx);
                const float* wr = wb + (c * 9 + tap) * 12;
                ulonglong2 wA = *reinterpret_cast<const ulonglong2*>(wr);
                ulonglong2 wB = *reinterpret_cast<const ulonglong2*>(wr + 4);
                ull wC = *reinterpret_cast<const ull*>(wr + 8);
                o2[0][q] = ffma2(wA.x, fc, o2[0][q]);
                o2[1][q] = ffma2(wA.y, fc, o2[1][q]);
                o2[2][q] = ffma2(wB.x, fc, o2[2][q]);
                o2[3][q] = ffma2(wB.y, fc, o2[3][q]);
                o2[4][q] = ffma2(wC,   fc, o2[4][q]);
            }
        }
    }
}

// ==================== K1: gather + conv1 + pool + conv2 ====================
__global__ void __launch_bounds__(TPB, 3)
conv_kernel(const int* __restrict__ state, const int* __restrict__ des,
            const int* __restrict__ asp, const int* __restrict__ pm,
            const float* __restrict__ path_feature,
            const float* __restrict__ link_feature,
            const float* __restrict__ c1w, const float* __restrict__ c1b,
            const float* __restrict__ c2w, const float* __restrict__ c2b,
            int B)
{
    extern __shared__ float sm[];
    const int tid = threadIdx.x;

    for (int i = tid; i < 4536; i += TPB) {            // W1 [half][c][tap][12]
        int half = i / 2268; int rem = i % 2268;
        int c = rem / 108; int rem2 = rem % 108;
        int tap = rem2 / 12; int j = rem2 % 12;
        sm[W1_OFF + i] = (j < 10) ? c1w[((half * 10 + j) * 21 + c) * 9 + tap] : 0.f;
    }
    for (int i = tid; i < 2560; i += TPB) {            // W2 [oc][q][oc2 pad 32]
        int oc = i / 128; int rem = i % 128; int q = rem / 32; int oc2 = rem % 32;
        sm[W2_OFF + i] = (oc2 < 30) ? c2w[(oc2 * 20 + oc) * 4 + q] : 0.f;
    }
    if (tid < 20) sm[B1_OFF + tid] = c1b[tid];
    if (tid < 32) sm[B2P_OFF + tid] = (tid < 30) ? c2b[tid] : 0.f;
    __syncthreads();

    const int b = blockIdx.x * TPB + tid;
    if (b >= B) return;

    const int s = state[b];
    const size_t dd = (size_t)des[b];

    int nn[9];
    float mf[9];
#pragma unroll
    for (int r = 0; r < 9; ++r) {
        nn[r] = asp[s * 9 + r];
        mf[r] = (float)pm[s * 9 + r];
    }

    float* Fb = sm + FB_OFF + tid * 21;   // stride 21 (coprime with 32) -> conflict-free

    ull o2[5][9];
    ull aa[16];

    float4 v0, v1, v2, v3, v4;
#define LOADN(r) { \
        const float4* pf4 = reinterpret_cast<const float4*>( \
            path_feature + ((size_t)nn[r] * 300 + dd) * 12); \
        v0 = pf4[0]; v1 = pf4[1]; v2 = pf4[2]; \
        const float4* lf4 = reinterpret_cast<const float4*>(link_feature + (size_t)nn[r] * 8); \
        v3 = lf4[0]; v4 = lf4[1]; }
#define PUSHF(r) { \
        Fb[0] = v0.x;  Fb[1] = v0.y;  Fb[2] = v0.z;  Fb[3] = v0.w; \
        Fb[4] = v1.x;  Fb[5] = v1.y;  Fb[6] = v1.z;  Fb[7] = v1.w; \
        Fb[8] = v2.x;  Fb[9] = v2.y;  Fb[10] = v2.z; Fb[11] = v2.w; \
        Fb[12] = v3.x; Fb[13] = v3.y; Fb[14] = v3.z; Fb[15] = v3.w; \
        Fb[16] = v4.x; Fb[17] = v4.y; Fb[18] = v4.z; Fb[19] = v4.w; \
        Fb[20] = mf[r]; }

    // neighbor r -> grid position invp[r] = {1,2,5,8,7,6,3,0,4}
#define CONV_PASS(WB) \
    LOADN(0); \
    PUSHF(0); LOADN(1); nconvh<0,1>(WB, Fb, o2); \
    PUSHF(1); LOADN(2); nconvh<0,2>(WB, Fb, o2); \
    PUSHF(2); LOADN(3); nconvh<1,2>(WB, Fb, o2); \
    PUSHF(3); LOADN(4); nconvh<2,2>(WB, Fb, o2); \
    PUSHF(4); LOADN(5); nconvh<2,1>(WB, Fb, o2); \
    PUSHF(5); LOADN(6); nconvh<2,0>(WB, Fb, o2); \
    PUSHF(6); LOADN(7); nconvh<1,0>(WB, Fb, o2); \
    PUSHF(7); LOADN(8); nconvh<0,0>(WB, Fb, o2); \
    PUSHF(8);           nconvh<1,1>(WB, Fb, o2);

    // lrelu + 2x2/s1 maxpool + conv2 accumulate for one conv1 channel
#define POOLC(ARR, OC) { \
    float r0 = lrelu(ARR[0]), r1 = lrelu(ARR[1]), r2 = lrelu(ARR[2]); \
    float r3 = lrelu(ARR[3]), r4 = lrelu(ARR[4]), r5 = lrelu(ARR[5]); \
    float r6 = lrelu(ARR[6]), r7 = lrelu(ARR[7]), r8 = lrelu(ARR[8]); \
    float pq4[4]; \
    pq4[0] = fmaxf(fmaxf(r0, r1), fmaxf(r3, r4)); \
    pq4[1] = fmaxf(fmaxf(r1, r2), fmaxf(r4, r5)); \
    pq4[2] = fmaxf(fmaxf(r3, r4), fmaxf(r6, r7)); \
    pq4[3] = fmaxf(fmaxf(r4, r5), fmaxf(r7, r8)); \
    _Pragma("unroll") \
    for (int q = 0; q < 4; ++q) { \
        ull pq = pack2(pq4[q], pq4[q]); \
        const ulonglong2* wp = reinterpret_cast<const ulonglong2*>( \
            sm + W2_OFF + ((OC) * 4 + q) * 32); \
        _Pragma("unroll") \
        for (int g = 0; g < 8; ++g) { \
            ulonglong2 w = wp[g]; \
            aa[2 * g]     = ffma2(w.x, pq, aa[2 * g]); \
            aa[2 * g + 1] = ffma2(w.y, pq, aa[2 * g + 1]); \
        } } }

#define POOLHALF(OCBASE) { \
    _Pragma("unroll") \
    for (int u = 0; u < 5; ++u) { \
        float l[9], h[9]; \
        _Pragma("unroll") \
        for (int q = 0; q < 9; ++q) unpack2(o2[u][q], l[q], h[q]); \
        POOLC(l, (OCBASE) + 2 * u) \
        POOLC(h, (OCBASE) + 2 * u + 1) } }

    // ---------- half 0 : oc 0..9 ----------
#pragma unroll
    for (int u = 0; u < 5; ++u) {
        ull bb = pack2(sm[B1_OFF + 2 * u], sm[B1_OFF + 2 * u + 1]);
#pragma unroll
        for (int q = 0; q < 9; ++q) o2[u][q] = bb;
    }
    CONV_PASS(sm + W1_OFF);
#pragma unroll
    for (int j = 0; j < 16; ++j)
        aa[j] = pack2(sm[B2P_OFF + 2 * j], sm[B2P_OFF + 2 * j + 1]);
    POOLHALF(0);

    // ---------- half 1 : oc 10..19 (re-gather, hits L2) ----------
#pragma unroll
    for (int u = 0; u < 5; ++u) {
        ull bb = pack2(sm[B1_OFF + 10 + 2 * u], sm[B1_OFF + 11 + 2 * u]);
#pragma unroll
        for (int q = 0; q < 9; ++q) o2[u][q] = bb;
    }
    CONV_PASS(sm + W1_OFF + 2268);
    POOLHALF(10);

#undef LOADN
#undef PUSHF
#undef CONV_PASS
#undef POOLC
#undef POOLHALF

    // ---------- lrelu + store 30 (+2 pad) floats to scratch ----------
    float* sp = g_scratch + (size_t)b * 32;
#pragma unroll
    for (int j = 0; j < 15; ++j) {
        float lo, hi; unpack2(aa[j], lo, hi);
        float2 st; st.x = lrelu(lo); st.y = lrelu(hi);
        *reinterpret_cast<float2*>(sp + 2 * j) = st;
    }
    float2 zz; zz.x = 0.f; zz.y = 0.f;
    *reinterpret_cast<float2*>(sp + 30) = zz;
}

// ==================== K2: fc1 + fc2 + fc3 + sigmoid ====================
__global__ void __launch_bounds__(TPB, 3)
fc_kernel(const int* __restrict__ act,
          const float* __restrict__ f1w, const float* __restrict__ f1b,
          const float* __restrict__ f2w, const float* __restrict__ f2b,
          const float* __restrict__ f3w, const float* __restrict__ f3b,
          float* __restrict__ out, int B)
{
    extern __shared__ float sm[];
    const int tid = threadIdx.x;

    for (int i = tid; i < 3840; i += TPB) {            // FC1 [j1][32]
        int j = i / 32; int k = i % 32;
        sm[FC1P_OFF + i] = (k < 30) ? f1w[j * 38 + k] : 0.f;
    }
    for (int i = tid; i < 960; i += TPB) {             // FC1 one-hot cols
        int j = i / 8; int a8 = i % 8;
        sm[FC1OH_OFF + i] = f1w[j * 38 + 30 + a8];
    }
    for (int i = tid; i < 10080; i += TPB) {           // FC2 transposed [j1][84]
        int j1 = i / 84; int j2 = i % 84;
        sm[FC2T_OFF + i] = f2w[j2 * 120 + j1];
    }
    for (int i = tid; i < 84; i += TPB) sm[FC3_OFF + i] = f3w[i];
    if (tid < 120) sm[FB1_OFF + tid] = f1b[tid];
    if (tid < 84) sm[FB2_OFF + tid] = f2b[tid];
    if (tid == 0) sm[FB3_OFF] = f3b[0];
    __syncthreads();

    const int b = blockIdx.x * TPB + tid;
    if (b >= B) return;

    const int a = act[b];

    // load 32 floats (30 valid + 2 zero pads) as 16 fp32x2 pairs
    const float* sp = g_scratch + (size_t)b * 32;
    ull x2[16];
#pragma unroll
    for (int g = 0; g < 8; ++g) {
        float4 v = *reinterpret_cast<const float4*>(sp + 4 * g);
        x2[2 * g]     = pack2(v.x, v.y);
        x2[2 * g + 1] = pack2(v.z, v.w);
    }

    ull hh[42];
#pragma unroll
    for (int j = 0; j < 42; ++j)
        hh[j] = pack2(sm[FB2_OFF + 2 * j], sm[FB2_OFF + 2 * j + 1]);

#pragma unroll 2
    for (int j1 = 0; j1 < 120; ++j1) {
        const ulonglong2* wp = reinterpret_cast<const ulonglong2*>(sm + FC1P_OFF + j1 * 32);
        ull t0 = 0ull, t1 = 0ull, t2 = 0ull, t3 = 0ull;
#pragma unroll
        for (int g = 0; g < 4; ++g) {
            ulonglong2 wA = wp[2 * g], wB = wp[2 * g + 1];
            t0 = ffma2(wA.x, x2[4 * g],     t0);
            t1 = ffma2(wA.y, x2[4 * g + 1], t1);
            t2 = ffma2(wB.x, x2[4 * g + 2], t2);
            t3 = ffma2(wB.y, x2[4 * g + 3], t3);
        }
        float s0, s1, s2, s3, s4, s5, s6, s7;
        unpack2(t0, s0, s1); unpack2(t1, s2, s3); unpack2(t2, s4, s5); unpack2(t3, s6, s7);
        float t = sm[FB1_OFF + j1] + sm[FC1OH_OFF + j1 * 8 + a]
                + (((s0 + s1) + (s2 + s3)) + ((s4 + s5) + (s6 + s7)));
        t = lrelu(t);
        ull tt = pack2(t, t);
        const ulonglong2* w2p = reinterpret_cast<const ulonglong2*>(sm + FC2T_OFF + j1 * 84);
#pragma unroll
        for (int g = 0; g < 21; ++g) {
            ulonglong2 w = w2p[g];
            hh[2 * g]     = ffma2(w.x, tt, hh[2 * g]);
            hh[2 * g + 1] = ffma2(w.y, tt, hh[2 * g + 1]);
        }
    }

    float z0 = 0.f, z1 = 0.f, z2 = 0.f, z3 = 0.f;
#pragma unroll
    for (int g = 0; g < 42; ++g) {
        float lo, hi; unpack2(hh[g], lo, hi);
        lo = lrelu(lo); hi = lrelu(hi);
        if (g & 1) { z2 += lo * sm[FC3_OFF + 2 * g]; z3 += hi * sm[FC3_OFF + 2 * g + 1]; }
        else       { z0 += lo * sm[FC3_OFF + 2 * g]; z1 += hi * sm[FC3_OFF + 2 * g + 1]; }
    }
    float z = sm[FB3_OFF] + ((z0 + z1) + (z2 + z3));
    out[b] = 1.f / (1.f + expf(-z));
}

extern "C" void kernel_launch(void* const* d_in, const int* in_sizes, int n_in,
                              void* d_out, int out_size)
{
    const int*   state = (const int*)d_in[0];
    const int*   des   = (const int*)d_in[1];
    const int*   act   = (const int*)d_in[2];
    const int*   asp   = (const int*)d_in[3];
    const int*   pm    = (const int*)d_in[4];
    const float* pf    = (const float*)d_in[5];
    const float* lf    = (const float*)d_in[6];
    const float* c1w   = (const float*)d_in[7];
    const float* c1b   = (const float*)d_in[8];
    const float* c2w   = (const float*)d_in[9];
    const float* c2b   = (const float*)d_in[10];
    const float* f1w   = (const float*)d_in[11];
    const float* f1b   = (const float*)d_in[12];
    const float* f2w   = (const float*)d_in[13];
    const float* f2b   = (const float*)d_in[14];
    const float* f3w   = (const float*)d_in[15];
    const float* f3b   = (const float*)d_in[16];

    const int B = in_sizes[0];
    float* out = (float*)d_out;

    cudaFuncSetAttribute(conv_kernel, cudaFuncAttributeMaxDynamicSharedMemorySize, K1_BYTES);
    cudaFuncSetAttribute(fc_kernel,   cudaFuncAttributeMaxDynamicSharedMemorySize, K2_BYTES);

    const int grid = (B + TPB - 1) / TPB;
    conv_kernel<<<grid, TPB, K1_BYTES>>>(state, des, asp, pm, pf, lf,
                                         c1w, c1b, c2w, c2b, B);
    fc_kernel<<<grid, TPB, K2_BYTES>>>(act, f1w, f1b, f2w, f2b, f3w, f3b, out, B);
}

// round 8
// speedup vs baseline: 1.3006x; 1.3006x over previous
#include <cuda_runtime.h>
#include <math.h>

typedef unsigned long long ull;

#define TPB 128

// ---------------- constant-memory weights (65040 B total <= 64 KB) ----------------
// cW1 : conv1 [c][tap][oc20]    : 945 ul2  = 15120 B  (5 ul2 per (c,tap))
// cW2u: conv2 [oc][q][oc2(30)]  : 1200 ull = 9600 B   (15 ull per (oc,q))
// cFC2: fc2 transposed [j1][84] : 2520 ul2 = 40320 B  (21 ul2 per j1)
__constant__ ulonglong2 cW1[945];
__constant__ ull        cW2u[1200];
__constant__ ulonglong2 cFC2[2520];

// staging buffer the repack kernel fills; then D2D-copied into the symbols
__device__ float g_pack[16260];

// ---------------- shared memory float offsets (31.3 KB) ----------------
#define FC1P_OFF  0        // fc1 [j1][32] (cols 0..29, pad 0) : 3840
#define FC1OH_OFF 3840     // fc1 one-hot cols [j1][8] : 960
#define FC3_OFF   4800     // 84
#define B1_OFF    4884     // 20
#define B2P_OFF   4904     // 32
#define FB1_OFF   4936     // 120
#define FB2_OFF   5056     // 84
#define FB3_OFF   5140     // 1 (+3 pad)
#define FEAT_OFF  5144     // per-thread 21-float feature buffer
#define SMEM_FLOATS (FEAT_OFF + TPB * 21)   // 7832
#define SMEM_BYTES  (SMEM_FLOATS * 4)       // 31328

__device__ __forceinline__ ull ffma2(ull a, ull b, ull c) {
    ull d; asm("fma.rn.f32x2 %0,%1,%2,%3;" : "=l"(d) : "l"(a), "l"(b), "l"(c)); return d;
}
__device__ __forceinline__ ull pack2(float lo, float hi) {
    ull d; asm("mov.b64 %0,{%1,%2};" : "=l"(d) : "f"(lo), "f"(hi)); return d;
}
__device__ __forceinline__ void unpack2(ull v, float& lo, float& hi) {
    asm("mov.b64 {%0,%1},%2;" : "=f"(lo), "=f"(hi) : "l"(v));
}
__device__ __forceinline__ float lrelu(float v) { return fmaxf(v, 0.2f * v); }

// ==================== repack kernel: gmem weights -> g_pack ====================
__global__ void repack_kernel(const float* __restrict__ c1w,
                              const float* __restrict__ c2w,
                              const float* __restrict__ f2w)
{
    int i = blockIdx.x * 256 + threadIdx.x;
    if (i < 3780) {                       // W1 [c][tap][oc20]
        int c = i / 180; int rem = i % 180; int tap = rem / 20; int oc = rem % 20;
        g_pack[i] = c1w[(oc * 21 + c) * 9 + tap];
    } else if (i < 6180) {                // W2 [oc][q][oc2(30)] unpadded
        int j = i - 3780;
        int oc = j / 120; int rem = j % 120; int q = rem / 30; int oc2 = rem % 30;
        g_pack[i] = c2w[(oc2 * 20 + oc) * 4 + q];
    } else if (i < 16260) {               // FC2 transposed [j1][84]
        int j = i - 6180;
        int j1 = j / 84; int j2 = j % 84;
        g_pack[i] = f2w[j2 * 120 + j1];
    }
}

// conv1 contribution of the neighbor at grid position (PY,PX), all 20 oc.
// Weights read from __constant__ (uniform across warp -> constant/uniform port).
template<int PY, int PX>
__device__ __forceinline__ void nconv(const float* __restrict__ Fb,
                                      ull (&o2)[10][9]) {
#pragma unroll 3
    for (int c = 0; c < 21; ++c) {
        float fv = Fb[c];
        ull fc = pack2(fv, fv);
#pragma unroll
        for (int dy = -1; dy <= 1; ++dy) {
            if (PY + dy < 0 || PY + dy > 2) continue;
#pragma unroll
            for (int dx = -1; dx <= 1; ++dx) {
                if (PX + dx < 0 || PX + dx > 2) continue;
                const int tap = (1 - dy) * 3 + (1 - dx);
                const int q = (PY + dy) * 3 + (PX + dx);
                const int base = (c * 9 + tap) * 5;
                ulonglong2 w0 = cW1[base + 0];
                ulonglong2 w1 = cW1[base + 1];
                ulonglong2 w2 = cW1[base + 2];
                ulonglong2 w3 = cW1[base + 3];
                ulonglong2 w4 = cW1[base + 4];
                o2[0][q] = ffma2(w0.x, fc, o2[0][q]);
                o2[1][q] = ffma2(w0.y, fc, o2[1][q]);
                o2[2][q] = ffma2(w1.x, fc, o2[2][q]);
                o2[3][q] = ffma2(w1.y, fc, o2[3][q]);
                o2[4][q] = ffma2(w2.x, fc, o2[4][q]);
                o2[5][q] = ffma2(w2.y, fc, o2[5][q]);
                o2[6][q] = ffma2(w3.x, fc, o2[6][q]);
                o2[7][q] = ffma2(w3.y, fc, o2[7][q]);
                o2[8][q] = ffma2(w4.x, fc, o2[8][q]);
                o2[9][q] = ffma2(w4.y, fc, o2[9][q]);
            }
        }
    }
}

// lrelu + 2x2/s1 maxpool + conv2 accumulate for one conv1 channel.
// Scalars by value (no addressable arrays -> no local memory).
__device__ __forceinline__ void poolc2(float r0, float r1, float r2,
                                       float r3, float r4, float r5,
                                       float r6, float r7, float r8,
                                       int oc, ull (&aa)[16])
{
    r0 = lrelu(r0); r1 = lrelu(r1); r2 = lrelu(r2);
    r3 = lrelu(r3); r4 = lrelu(r4); r5 = lrelu(r5);
    r6 = lrelu(r6); r7 = lrelu(r7); r8 = lrelu(r8);
    float p0 = fmaxf(fmaxf(r0, r1), fmaxf(r3, r4));
    float p1 = fmaxf(fmaxf(r1, r2), fmaxf(r4, r5));
    float p2 = fmaxf(fmaxf(r3, r4), fmaxf(r6, r7));
    float p3 = fmaxf(fmaxf(r4, r5), fmaxf(r7, r8));
#pragma unroll
    for (int q = 0; q < 4; ++q) {
        float pv = (q == 0) ? p0 : (q == 1) ? p1 : (q == 2) ? p2 : p3;
        ull pq = pack2(pv, pv);
        const int base = (oc * 4 + q) * 15;   // 15 ull per (oc,q) row of 30 floats
#pragma unroll
        for (int g = 0; g < 15; ++g) {
            ull w = cW2u[base + g];
            aa[g] = ffma2(w, pq, aa[g]);
        }
    }
}

__global__ void __launch_bounds__(TPB, 2)
disc_kernel(const int* __restrict__ state, const int* __restrict__ des,
            const int* __restrict__ act,
            const int* __restrict__ asp, const int* __restrict__ pm,
            const float* __restrict__ path_feature,
            const float* __restrict__ link_feature,
            const float* __restrict__ c1b, const float* __restrict__ c2b,
            const float* __restrict__ f1w, const float* __restrict__ f1b,
            const float* __restrict__ f2b,
            const float* __restrict__ f3w, const float* __restrict__ f3b,
            float* __restrict__ out, int B)
{
    extern __shared__ float sm[];
    const int tid = threadIdx.x;

    // ---------- stage fc1 + small vectors into smem ----------
    for (int i = tid; i < 3840; i += TPB) {            // FC1 [j1][32]
        int j = i / 32; int k = i % 32;
        sm[FC1P_OFF + i] = (k < 30) ? f1w[j * 38 + k] : 0.f;
    }
    for (int i = tid; i < 960; i += TPB) {             // FC1 one-hot cols
        int j = i / 8; int a8 = i % 8;
        sm[FC1OH_OFF + i] = f1w[j * 38 + 30 + a8];
    }
    for (int i = tid; i < 84; i += TPB) sm[FC3_OFF + i] = f3w[i];
    if (tid < 20) sm[B1_OFF + tid] = c1b[tid];
    if (tid < 32) sm[B2P_OFF + tid] = (tid < 30) ? c2b[tid] : 0.f;
    if (tid < 120) sm[FB1_OFF + tid] = f1b[tid];
    if (tid < 84) sm[FB2_OFF + tid] = f2b[tid];
    if (tid == 0) sm[FB3_OFF] = f3b[0];
    __syncthreads();

    const int b = blockIdx.x * TPB + tid;
    if (b >= B) return;

    const int s = state[b];
    const size_t dd = (size_t)des[b];
    const int a = act[b];

    int nn[9];
    float mf[9];
#pragma unroll
    for (int r = 0; r < 9; ++r) {
        nn[r] = asp[s * 9 + r];
        mf[r] = (float)pm[s * 9 + r];
    }

    float* Fb = sm + FEAT_OFF + tid * 21;  // stride 21 (odd) -> conflict-free

    // conv1 accumulators: 20 oc as 10 fp32x2 pairs x 9 positions, init = bias
    ull o2[10][9];
#pragma unroll
    for (int u = 0; u < 10; ++u) {
        ull bb = pack2(sm[B1_OFF + 2 * u], sm[B1_OFF + 2 * u + 1]);
#pragma unroll
        for (int q = 0; q < 9; ++q) o2[u][q] = bb;
    }

    float4 v0, v1, v2, v3, v4;
#define LOADN(r) { \
        const float4* pf4 = reinterpret_cast<const float4*>( \
            path_feature + ((size_t)nn[r] * 300 + dd) * 12); \
        v0 = pf4[0]; v1 = pf4[1]; v2 = pf4[2]; \
        const float4* lf4 = reinterpret_cast<const float4*>(link_feature + (size_t)nn[r] * 8); \
        v3 = lf4[0]; v4 = lf4[1]; }
#define PUSHF(r) { \
        Fb[0] = v0.x;  Fb[1] = v0.y;  Fb[2] = v0.z;  Fb[3] = v0.w; \
        Fb[4] = v1.x;  Fb[5] = v1.y;  Fb[6] = v1.z;  Fb[7] = v1.w; \
        Fb[8] = v2.x;  Fb[9] = v2.y;  Fb[10] = v2.z; Fb[11] = v2.w; \
        Fb[12] = v3.x; Fb[13] = v3.y; Fb[14] = v3.z; Fb[15] = v3.w; \
        Fb[16] = v4.x; Fb[17] = v4.y; Fb[18] = v4.z; Fb[19] = v4.w; \
        Fb[20] = mf[r]; }

    // neighbor r sits at grid position invp[r] = {1,2,5,8,7,6,3,0,4}
    LOADN(0);
    PUSHF(0); LOADN(1); nconv<0,1>(Fb, o2);
    PUSHF(1); LOADN(2); nconv<0,2>(Fb, o2);
    PUSHF(2); LOADN(3); nconv<1,2>(Fb, o2);
    PUSHF(3); LOADN(4); nconv<2,2>(Fb, o2);
    PUSHF(4); LOADN(5); nconv<2,1>(Fb, o2);
    PUSHF(5); LOADN(6); nconv<2,0>(Fb, o2);
    PUSHF(6); LOADN(7); nconv<1,0>(Fb, o2);
    PUSHF(7); LOADN(8); nconv<0,0>(Fb, o2);
    PUSHF(8);           nconv<1,1>(Fb, o2);
#undef LOADN
#undef PUSHF

    // ---------- lrelu + maxpool + conv2 ----------
    ull aa[16];
#pragma unroll
    for (int j = 0; j < 16; ++j)
        aa[j] = pack2(sm[B2P_OFF + 2 * j], sm[B2P_OFF + 2 * j + 1]);

#pragma unroll
    for (int u = 0; u < 10; ++u) {
        float lo[9], hi[9];
#pragma unroll
        for (int q = 0; q < 9; ++q) unpack2(o2[u][q], lo[q], hi[q]);
        poolc2(lo[0], lo[1], lo[2], lo[3], lo[4], lo[5], lo[6], lo[7], lo[8], 2 * u,     aa);
        poolc2(hi[0], hi[1], hi[2], hi[3], hi[4], hi[5], hi[6], hi[7], hi[8], 2 * u + 1, aa);
    }

    // ---------- fc1 + fc2 fused ----------
    ull x2[16];
#pragma unroll
    for (int j = 0; j < 15; ++j) {
        float lo, hi; unpack2(aa[j], lo, hi);
        x2[j] = pack2(lrelu(lo), lrelu(hi));
    }
    x2[15] = pack2(0.f, 0.f);

    ull hh[42];
#pragma unroll
    for (int j = 0; j < 42; ++j)
        hh[j] = pack2(sm[FB2_OFF + 2 * j], sm[FB2_OFF + 2 * j + 1]);

#pragma unroll 2
    for (int j1 = 0; j1 < 120; ++j1) {
        const ulonglong2* wp = reinterpret_cast<const ulonglong2*>(sm + FC1P_OFF + j1 * 32);
        ull t0 = 0ull, t1 = 0ull, t2 = 0ull, t3 = 0ull;
#pragma unroll
        for (int g = 0; g < 4; ++g) {
            ulonglong2 wA = wp[2 * g], wB = wp[2 * g + 1];
            t0 = ffma2(wA.x, x2[4 * g],     t0);
            t1 = ffma2(wA.y, x2[4 * g + 1], t1);
            t2 = ffma2(wB.x, x2[4 * g + 2], t2);
            t3 = ffma2(wB.y, x2[4 * g + 3], t3);
        }
        float s0, s1, s2, s3, s4, s5, s6, s7;
        unpack2(t0, s0, s1); unpack2(t1, s2, s3); unpack2(t2, s4, s5); unpack2(t3, s6, s7);
        float t = sm[FB1_OFF + j1] + sm[FC1OH_OFF + j1 * 8 + a]
                + (((s0 + s1) + (s2 + s3)) + ((s4 + s5) + (s6 + s7)));
        t = lrelu(t);
        ull tt = pack2(t, t);
        const int fbase = j1 * 21;
#pragma unroll
        for (int g = 0; g < 21; ++g) {
            ulonglong2 w = cFC2[fbase + g];
            hh[2 * g]     = ffma2(w.x, tt, hh[2 * g]);
            hh[2 * g + 1] = ffma2(w.y, tt, hh[2 * g + 1]);
        }
    }

    // ---------- fc3 + sigmoid ----------
    float z0 = 0.f, z1 = 0.f, z2 = 0.f, z3 = 0.f;
#pragma unroll
    for (int g = 0; g < 42; ++g) {
        float lo, hi; unpack2(hh[g], lo, hi);
        lo = lrelu(lo); hi = lrelu(hi);
        if (g & 1) { z2 += lo * sm[FC3_OFF + 2 * g]; z3 += hi * sm[FC3_OFF + 2 * g + 1]; }
        else       { z0 += lo * sm[FC3_OFF + 2 * g]; z1 += hi * sm[FC3_OFF + 2 * g + 1]; }
    }
    float z = sm[FB3_OFF] + ((z0 + z1) + (z2 + z3));
    out[b] = 1.f / (1.f + expf(-z));
}

extern "C" void kernel_launch(void* const* d_in, const int* in_sizes, int n_in,
                              void* d_out, int out_size)
{
    const int*   state = (const int*)d_in[0];
    const int*   des   = (const int*)d_in[1];
    const int*   act   = (const int*)d_in[2];
    const int*   asp   = (const int*)d_in[3];
    const int*   pm    = (const int*)d_in[4];
    const float* pf    = (const float*)d_in[5];
    const float* lf    = (const float*)d_in[6];
    const float* c1w   = (const float*)d_in[7];
    const float* c1b   = (const float*)d_in[8];
    const float* c2w   = (const float*)d_in[9];
    const float* c2b   = (const float*)d_in[10];
    const float* f1w   = (const float*)d_in[11];
    const float* f1b   = (const float*)d_in[12];
    const float* f2w   = (const float*)d_in[13];
    const float* f2b   = (const float*)d_in[14];
    const float* f3w   = (const float*)d_in[15];
    const float* f3b   = (const float*)d_in[16];

    const int B = in_sizes[0];
    float* out = (float*)d_out;

    // repack weights into g_pack, then D2D-copy into __constant__ symbols
    repack_kernel<<<(16260 + 255) / 256, 256>>>(c1w, c2w, f2w);

    void* ps = nullptr;
    cudaGetSymbolAddress(&ps, g_pack);
    const char* pc = (const char*)ps;
    cudaMemcpyToSymbolAsync(cW1,  pc,            945 * 16,  0, cudaMemcpyDeviceToDevice);
    cudaMemcpyToSymbolAsync(cW2u, pc + 3780 * 4, 1200 * 8,  0, cudaMemcpyDeviceToDevice);
    cudaMemcpyToSymbolAsync(cFC2, pc + 6180 * 4, 2520 * 16, 0, cudaMemcpyDeviceToDevice);

    const int grid = (B + TPB - 1) / TPB;
    disc_kernel<<<grid, TPB, SMEM_BYTES>>>(state, des, act, asp, pm, pf, lf,
                                           c1b, c2b, f1w, f1b, f2b, f3w, f3b,
                                           out, B);
}